// round 2
// baseline (speedup 1.0000x reference)
#include <cuda_runtime.h>
#include <math.h>

// Problem shape (known from reference; derived dynamically at launch too)
#define B_MAX 16384
#define C_MAX 1000
#define D_MAX 2048

// Scratch (no cudaMalloc allowed) — ~78 MB of __device__ globals.
__device__ float g_phat[(size_t)C_MAX * D_MAX];          // prototype / ||prototype||
__device__ float g_qn[B_MAX];                            // ||querys|| per row (clamped)
__device__ float g_scores[(size_t)B_MAX * C_MAX];        // q . phat^T, then attn in-place
__device__ float g_Mt[(size_t)C_MAX * C_MAX];            // Mt[j][c] = sum_d W[j,d] P[c,d]

// ---------------------------------------------------------------------------
// Tiled fp32 NT GEMM: C[m,n] (+)= sum_k A[m,k] * B[n,k]  (both row-major)
// 128x128 tile, BK=16, 256 threads, 8x8 per thread. Handles ragged M/N/K.
// ---------------------------------------------------------------------------
__global__ void __launch_bounds__(256, 2)
gemm_nt_kernel(const float* __restrict__ A, int lda,
               const float* __restrict__ B, int ldb,
               float* __restrict__ C, int ldc,
               const float* __restrict__ bias,
               int M, int N, int K, int accumulate)
{
    __shared__ float As[16][128];
    __shared__ float Bs[16][128];

    const int t  = threadIdx.x;
    const int tx = t & 15;   // n-dir
    const int ty = t >> 4;   // m-dir
    const int m0 = blockIdx.y * 128;
    const int n0 = blockIdx.x * 128;

    float acc[8][8];
#pragma unroll
    for (int i = 0; i < 8; ++i)
#pragma unroll
        for (int j = 0; j < 8; ++j) acc[i][j] = 0.f;

    for (int k0 = 0; k0 < K; k0 += 16) {
        // ---- load A/B tiles (128 rows x 16 k) transposed into s[k][row] ----
#pragma unroll
        for (int p = 0; p < 2; ++p) {
            int v  = t + p * 256;        // 0..511 vector slots
            int r  = v >> 2;             // tile row 0..127
            int cv = (v & 3) << 2;       // k offset 0,4,8,12
            {
                int gm = m0 + r, gk = k0 + cv;
                float4 val = make_float4(0.f, 0.f, 0.f, 0.f);
                if (gm < M) {
                    if (gk + 3 < K) {
                        val = *reinterpret_cast<const float4*>(A + (size_t)gm * lda + gk);
                    } else {
                        float tmp[4] = {0.f, 0.f, 0.f, 0.f};
#pragma unroll
                        for (int j = 0; j < 4; ++j)
                            if (gk + j < K) tmp[j] = A[(size_t)gm * lda + gk + j];
                        val = make_float4(tmp[0], tmp[1], tmp[2], tmp[3]);
                    }
                }
                As[cv + 0][r] = val.x; As[cv + 1][r] = val.y;
                As[cv + 2][r] = val.z; As[cv + 3][r] = val.w;
            }
            {
                int gn = n0 + r, gk = k0 + cv;
                float4 val = make_float4(0.f, 0.f, 0.f, 0.f);
                if (gn < N) {
                    if (gk + 3 < K) {
                        val = *reinterpret_cast<const float4*>(B + (size_t)gn * ldb + gk);
                    } else {
                        float tmp[4] = {0.f, 0.f, 0.f, 0.f};
#pragma unroll
                        for (int j = 0; j < 4; ++j)
                            if (gk + j < K) tmp[j] = B[(size_t)gn * ldb + gk + j];
                        val = make_float4(tmp[0], tmp[1], tmp[2], tmp[3]);
                    }
                }
                Bs[cv + 0][r] = val.x; Bs[cv + 1][r] = val.y;
                Bs[cv + 2][r] = val.z; Bs[cv + 3][r] = val.w;
            }
        }
        __syncthreads();

        // ---- compute ----
#pragma unroll
        for (int k = 0; k < 16; ++k) {
            float4 a0 = *reinterpret_cast<const float4*>(&As[k][ty * 8]);
            float4 a1 = *reinterpret_cast<const float4*>(&As[k][ty * 8 + 4]);
            float4 b0 = *reinterpret_cast<const float4*>(&Bs[k][tx * 8]);
            float4 b1 = *reinterpret_cast<const float4*>(&Bs[k][tx * 8 + 4]);
            float a[8] = {a0.x, a0.y, a0.z, a0.w, a1.x, a1.y, a1.z, a1.w};
            float b[8] = {b0.x, b0.y, b0.z, b0.w, b1.x, b1.y, b1.z, b1.w};
#pragma unroll
            for (int i = 0; i < 8; ++i)
#pragma unroll
                for (int j = 0; j < 8; ++j)
                    acc[i][j] = fmaf(a[i], b[j], acc[i][j]);
        }
        __syncthreads();
    }

    // ---- epilogue ----
#pragma unroll
    for (int i = 0; i < 8; ++i) {
        int gm = m0 + ty * 8 + i;
        if (gm >= M) continue;
#pragma unroll
        for (int j = 0; j < 8; ++j) {
            int gn = n0 + tx * 8 + j;
            if (gn >= N) continue;
            float v = acc[i][j];
            if (bias) v += __ldg(&bias[gn]);
            size_t idx = (size_t)gm * ldc + gn;
            if (accumulate) C[idx] += v;
            else            C[idx] = v;
        }
    }
}

// ---------------------------------------------------------------------------
// Row L2 norms of querys, clamped to EPS
// ---------------------------------------------------------------------------
__global__ void __launch_bounds__(256)
qnorm_kernel(const float* __restrict__ q, float* __restrict__ qn, int D)
{
    __shared__ float red[8];
    const int row = blockIdx.x;
    const float4* x = reinterpret_cast<const float4*>(q + (size_t)row * D);
    float s = 0.f;
    for (int i = threadIdx.x; i < D / 4; i += 256) {
        float4 v = x[i];
        s += v.x * v.x + v.y * v.y + v.z * v.z + v.w * v.w;
    }
#pragma unroll
    for (int o = 16; o > 0; o >>= 1) s += __shfl_xor_sync(~0u, s, o);
    if ((threadIdx.x & 31) == 0) red[threadIdx.x >> 5] = s;
    __syncthreads();
    if (threadIdx.x == 0) {
        float tot = 0.f;
#pragma unroll
        for (int w = 0; w < 8; ++w) tot += red[w];
        qn[row] = fmaxf(sqrtf(tot), 1e-8f);
    }
}

// ---------------------------------------------------------------------------
// phat = prototype / max(||prototype||, EPS) per row
// ---------------------------------------------------------------------------
__global__ void __launch_bounds__(256)
phat_kernel(const float* __restrict__ p, float* __restrict__ phat, int D)
{
    __shared__ float red[8];
    __shared__ float s_inv;
    const int row = blockIdx.x;
    const float4* x = reinterpret_cast<const float4*>(p + (size_t)row * D);
    float4* y = reinterpret_cast<float4*>(phat + (size_t)row * D);
    float s = 0.f;
    for (int i = threadIdx.x; i < D / 4; i += 256) {
        float4 v = x[i];
        s += v.x * v.x + v.y * v.y + v.z * v.z + v.w * v.w;
    }
#pragma unroll
    for (int o = 16; o > 0; o >>= 1) s += __shfl_xor_sync(~0u, s, o);
    if ((threadIdx.x & 31) == 0) red[threadIdx.x >> 5] = s;
    __syncthreads();
    if (threadIdx.x == 0) {
        float tot = 0.f;
#pragma unroll
        for (int w = 0; w < 8; ++w) tot += red[w];
        s_inv = 1.f / fmaxf(sqrtf(tot), 1e-8f);
    }
    __syncthreads();
    const float inv = s_inv;
    for (int i = threadIdx.x; i < D / 4; i += 256) {
        float4 v = x[i];
        y[i] = make_float4(v.x * inv, v.y * inv, v.z * inv, v.w * inv);
    }
}

// ---------------------------------------------------------------------------
// In-place: scores[b,:] -> softmax(scores[b,:]/qn[b] / 0.2), zeroed if
// sum(cos) == 0 (reference's nonzero mask). One block per row, C <= 1024.
// Separate shared slots per reduction (no reuse hazards).
// ---------------------------------------------------------------------------
__global__ void __launch_bounds__(256)
softmax_mask_kernel(float* __restrict__ scores, const float* __restrict__ qn, int C)
{
    __shared__ float red[8];
    __shared__ float s_max, s_cossum, s_denom;
    const int row = blockIdx.x;
    const int t = threadIdx.x;
    float* s = scores + (size_t)row * C;
    const float invq = 1.f / qn[row];

    float vals[4];
    float lmax = -1e30f, lsum = 0.f;
#pragma unroll
    for (int it = 0; it < 4; ++it) {
        int i = t + it * 256;
        if (i < C) {
            float v = s[i] * invq;
            vals[it] = v;
            lmax = fmaxf(lmax, v);
            lsum += v;
        } else vals[it] = 0.f;
    }
    // block max
#pragma unroll
    for (int o = 16; o > 0; o >>= 1) lmax = fmaxf(lmax, __shfl_xor_sync(~0u, lmax, o));
    if ((t & 31) == 0) red[t >> 5] = lmax;
    __syncthreads();
    if (t == 0) {
        float m = red[0];
#pragma unroll
        for (int w = 1; w < 8; ++w) m = fmaxf(m, red[w]);
        s_max = m;
    }
    __syncthreads();
    const float rmax = s_max;

    // block sum of cos (for the nonzero mask)
#pragma unroll
    for (int o = 16; o > 0; o >>= 1) lsum += __shfl_xor_sync(~0u, lsum, o);
    if ((t & 31) == 0) red[t >> 5] = lsum;
    __syncthreads();
    if (t == 0) {
        float m = 0.f;
#pragma unroll
        for (int w = 0; w < 8; ++w) m += red[w];
        s_cossum = m;
    }
    __syncthreads();
    const float rowsum = s_cossum;

    // exp + denom
    float e[4];
    float lexp = 0.f;
#pragma unroll
    for (int it = 0; it < 4; ++it) {
        int i = t + it * 256;
        if (i < C) {
            e[it] = expf((vals[it] - rmax) * 5.0f);  // /0.2 temperature
            lexp += e[it];
        } else e[it] = 0.f;
    }
#pragma unroll
    for (int o = 16; o > 0; o >>= 1) lexp += __shfl_xor_sync(~0u, lexp, o);
    if ((t & 31) == 0) red[t >> 5] = lexp;
    __syncthreads();
    if (t == 0) {
        float m = 0.f;
#pragma unroll
        for (int w = 0; w < 8; ++w) m += red[w];
        s_denom = m;
    }
    __syncthreads();
    const float denom = s_denom;
    const float scale = (rowsum != 0.0f) ? (1.f / denom) : 0.f;
#pragma unroll
    for (int it = 0; it < 4; ++it) {
        int i = t + it * 256;
        if (i < C) s[i] = e[it] * scale;
    }
}

// ---------------------------------------------------------------------------
// Launch: logits = q.W^T + b + attn.(W.P^T)^T ;  embedding = q (copy)
// ---------------------------------------------------------------------------
extern "C" void kernel_launch(void* const* d_in, const int* in_sizes, int n_in,
                              void* d_out, int out_size)
{
    const float* q    = (const float*)d_in[0];
    const float* p    = (const float*)d_in[1];
    const float* w    = (const float*)d_in[2];
    const float* bias = (const float*)d_in[3];
    float* out = (float*)d_out;

    const int C = in_sizes[3];               // 1000
    const int D = in_sizes[1] / C;           // 2048
    const int B = in_sizes[0] / D;           // 16384

    float *phat, *qn, *scores, *Mt;
    cudaGetSymbolAddress((void**)&phat,   g_phat);
    cudaGetSymbolAddress((void**)&qn,     g_qn);
    cudaGetSymbolAddress((void**)&scores, g_scores);
    cudaGetSymbolAddress((void**)&Mt,     g_Mt);

    float* logits = out;                     // [B, C]
    float* emb    = out + (size_t)B * C;     // [B, D]

    dim3 blk(256);

    // norms / normalized prototypes
    qnorm_kernel<<<B, blk>>>(q, qn, D);
    phat_kernel<<<C, blk>>>(p, phat, D);

    // Mt[j][c] = sum_d W[j,d] * P[c,d]   (small 1000x1000x2048)
    dim3 gMt((C + 127) / 128, (C + 127) / 128);
    gemm_nt_kernel<<<gMt, blk>>>(w, D, p, D, Mt, C, nullptr, C, C, D, 0);

    // scores = q . phat^T   (16384x1000x2048)
    dim3 gBC((C + 127) / 128, (B + 127) / 128);
    gemm_nt_kernel<<<gBC, blk>>>(q, D, phat, D, scores, C, nullptr, B, C, D, 0);

    // scores -> attn (in-place softmax with qn scaling + nonzero mask)
    softmax_mask_kernel<<<B, blk>>>(scores, qn, C);

    // logits = q.W^T + bias   (16384x1000x2048)
    gemm_nt_kernel<<<gBC, blk>>>(q, D, w, D, logits, C, bias, B, C, D, 0);

    // logits += attn . Mt  (16384x1000x1000; Mt[j][c] indexed as NT B-operand)
    gemm_nt_kernel<<<gBC, blk>>>(scores, C, Mt, C, logits, C, nullptr, B, C, C, 1);

    // embedding output = querys
    cudaMemcpyAsync(emb, q, (size_t)B * D * sizeof(float), cudaMemcpyDeviceToDevice);
}

// round 4
// speedup vs baseline: 3.5962x; 3.5962x over previous
#include <cuda_runtime.h>
#include <cuda_bf16.h>
#include <cstdint>
#include <math.h>

#define BQ 16384
#define CC 1000
#define DD 2048
#define CP 1024        // padded C
#define NBROWS 2048    // phat rows [0,1000) + W rows [1000,2000) + zero pad

// ---------------- scratch (__device__ globals) ----------------
__device__ __align__(128) __nv_bfloat16 g_q_hi[(size_t)BQ * DD];
__device__ __align__(128) __nv_bfloat16 g_q_lo[(size_t)BQ * DD];
__device__ __align__(128) __nv_bfloat16 g_b_hi[(size_t)NBROWS * DD];
__device__ __align__(128) __nv_bfloat16 g_b_lo[(size_t)NBROWS * DD];
__device__ __align__(128) __nv_bfloat16 g_mt_hi[(size_t)CP * CP];
__device__ __align__(128) __nv_bfloat16 g_mt_lo[(size_t)CP * CP];
__device__ __align__(128) __nv_bfloat16 g_at_hi[(size_t)BQ * CP];
__device__ __align__(128) __nv_bfloat16 g_at_lo[(size_t)BQ * CP];
__device__ float g_scores[(size_t)BQ * CC];
__device__ float g_mt[(size_t)CP * CP];
__device__ float g_qn[BQ];
__device__ float g_pn[CP];

// ---------------- PTX helpers (sm_80-era, no 'a'-gated features) ----------------
__device__ __forceinline__ uint32_t smem_u32(const void* p) {
    uint32_t a;
    asm("{ .reg .u64 t; cvta.to.shared.u64 t, %1; cvt.u32.u64 %0, t; }" : "=r"(a) : "l"(p));
    return a;
}
__device__ __forceinline__ void cp_async16(uint32_t dst, const void* src) {
    asm volatile("cp.async.cg.shared.global [%0], [%1], 16;" :: "r"(dst), "l"(src) : "memory");
}
__device__ __forceinline__ void ldmx4(uint32_t* r, uint32_t addr) {
    asm volatile("ldmatrix.sync.aligned.m8n8.x4.shared.b16 {%0,%1,%2,%3}, [%4];"
                 : "=r"(r[0]), "=r"(r[1]), "=r"(r[2]), "=r"(r[3]) : "r"(addr));
}
__device__ __forceinline__ void mma16816(float* d, const uint32_t* a, const uint32_t* b) {
    asm volatile("mma.sync.aligned.m16n8k16.row.col.f32.bf16.bf16.f32 "
        "{%0,%1,%2,%3}, {%4,%5,%6,%7}, {%8,%9}, {%0,%1,%2,%3};"
        : "+f"(d[0]), "+f"(d[1]), "+f"(d[2]), "+f"(d[3])
        : "r"(a[0]), "r"(a[1]), "r"(a[2]), "r"(a[3]), "r"(b[0]), "r"(b[1]));
}

// ---------------------------------------------------------------------------
// Split-bf16 HMMA GEMM: out[m,n] ~= sum_k A[m,k]*B[n,k] in fp32 precision via
// acc += Ah*Bh + Ah*Bl + Al*Bh.  128x128 CTA tile, BK=64, 8 warps (2m x 4n),
// warp tile 64x32, 3-stage cp.async pipeline, register accumulators.
// mode 0: out0[m*CP+n]  = v * aux[n]
// mode 1: n<CC -> out0[m*CC+n]=v ; CC<=n<2CC -> out1[m*CC+(n-CC)] = v+aux[n-CC]
// mode 2: n<CC -> out0[m*CC+n] += v
// ---------------------------------------------------------------------------
#define STAGES 3
#define SUB_B 16384                       // one 128-row x 128-byte subtile
#define STAGE_B (4 * SUB_B)               // Ahi, Alo, Bhi, Blo
#define SMEM_BYTES (STAGES * STAGE_B)     // 196608

__device__ __forceinline__ void load_stage(
    uint32_t stage, int tid,
    const __nv_bfloat16* Ah, const __nv_bfloat16* Al, int lda, int m0,
    const __nv_bfloat16* Bh, const __nv_bfloat16* Bl, int ldb, int n0, int k0)
{
#pragma unroll
    for (int ii = 0; ii < 16; ++ii) {
        const int sub = ii >> 2;                    // 0:Ah 1:Al 2:Bh 3:Bl
        const int rem = (ii & 3) * 256 + tid;       // 0..1023 within subtile
        const int row = rem >> 3;
        const int ch  = rem & 7;
        const uint32_t dst = stage + sub * SUB_B + row * 128 + ((ch ^ (row & 7)) << 4);
        const __nv_bfloat16* src;
        if (sub == 0)      src = Ah + (size_t)(m0 + row) * lda + k0 + ch * 8;
        else if (sub == 1) src = Al + (size_t)(m0 + row) * lda + k0 + ch * 8;
        else if (sub == 2) src = Bh + (size_t)(n0 + row) * ldb + k0 + ch * 8;
        else               src = Bl + (size_t)(n0 + row) * ldb + k0 + ch * 8;
        cp_async16(dst, src);
    }
    asm volatile("cp.async.commit_group;" ::: "memory");
}

__global__ void __launch_bounds__(256, 1)
mm_split_kernel(const __nv_bfloat16* __restrict__ Ahi, const __nv_bfloat16* __restrict__ Alo, int lda,
                const __nv_bfloat16* __restrict__ Bhi, const __nv_bfloat16* __restrict__ Blo, int ldb,
                int K,
                float* __restrict__ out0, float* __restrict__ out1,
                const float* __restrict__ aux, int mode)
{
    extern __shared__ __align__(1024) char smem[];
    const uint32_t sb = smem_u32(smem);
    const int tid  = threadIdx.x;
    const int wid  = tid >> 5, lane = tid & 31;
    const int m0 = blockIdx.y * 128, n0 = blockIdx.x * 128;
    const int nch = K >> 6;
    const int wm = wid & 1;        // 0..1  -> m offset wm*64
    const int wn = wid >> 1;       // 0..3  -> n offset wn*32

    // per-thread ldmatrix row indices (within CTA tile)
    uint32_t a_row[4], b_row[2];
#pragma unroll
    for (int mf = 0; mf < 4; ++mf) a_row[mf] = wm * 64 + mf * 16 + (lane & 15);
#pragma unroll
    for (int nf2 = 0; nf2 < 2; ++nf2)
        b_row[nf2] = wn * 32 + nf2 * 16 + (lane & 7) + ((lane >> 4) << 3);
    const uint32_t a_kc = (lane >> 4);        // 0/1
    const uint32_t b_kc = (lane >> 3) & 1;    // 0/1

    float acc[4][4][4];
#pragma unroll
    for (int i = 0; i < 4; ++i)
#pragma unroll
        for (int j = 0; j < 4; ++j)
#pragma unroll
            for (int r = 0; r < 4; ++r) acc[i][j][r] = 0.f;

    // prologue: stages 0,1
    load_stage(sb, tid, Ahi, Alo, lda, m0, Bhi, Blo, ldb, n0, 0);
    if (nch > 1) load_stage(sb + STAGE_B, tid, Ahi, Alo, lda, m0, Bhi, Blo, ldb, n0, 64);

    for (int i = 0; i < nch; ++i) {
        const int s = i % STAGES;
        if (i + 2 <= nch && nch > 1) asm volatile("cp.async.wait_group 1;" ::: "memory");
        else                         asm volatile("cp.async.wait_group 0;" ::: "memory");
        __syncthreads();

        // prefetch chunk i+2 (stage being overwritten was consumed at iter i-1)
        const int nx = i + 2;
        if (nx < nch)
            load_stage(sb + (nx % STAGES) * STAGE_B, tid,
                       Ahi, Alo, lda, m0, Bhi, Blo, ldb, n0, nx * 64);

        const uint32_t sA_hi = sb + s * STAGE_B;
        const uint32_t sA_lo = sA_hi + SUB_B;
        const uint32_t sB_hi = sA_hi + 2 * SUB_B;
        const uint32_t sB_lo = sA_hi + 3 * SUB_B;

#pragma unroll
        for (int st = 0; st < 4; ++st) {
            uint32_t ahi[4][4], alo[4][4];
#pragma unroll
            for (int mf = 0; mf < 4; ++mf) {
                const uint32_t r  = a_row[mf];
                const uint32_t kc = st * 2 + a_kc;
                const uint32_t off = r * 128 + (((kc ^ (r & 7))) << 4);
                ldmx4(ahi[mf], sA_hi + off);
                ldmx4(alo[mf], sA_lo + off);
            }
            uint32_t bhi[2][4], blo[2][4];
#pragma unroll
            for (int nf2 = 0; nf2 < 2; ++nf2) {
                const uint32_t r  = b_row[nf2];
                const uint32_t kc = st * 2 + b_kc;
                const uint32_t off = r * 128 + (((kc ^ (r & 7))) << 4);
                ldmx4(bhi[nf2], sB_hi + off);
                ldmx4(blo[nf2], sB_lo + off);
            }
#pragma unroll
            for (int mf = 0; mf < 4; ++mf)
#pragma unroll
                for (int nf2 = 0; nf2 < 2; ++nf2) {
                    mma16816(acc[mf][nf2 * 2],     ahi[mf], &bhi[nf2][0]);
                    mma16816(acc[mf][nf2 * 2],     ahi[mf], &blo[nf2][0]);
                    mma16816(acc[mf][nf2 * 2],     alo[mf], &bhi[nf2][0]);
                    mma16816(acc[mf][nf2 * 2 + 1], ahi[mf], &bhi[nf2][2]);
                    mma16816(acc[mf][nf2 * 2 + 1], ahi[mf], &blo[nf2][2]);
                    mma16816(acc[mf][nf2 * 2 + 1], alo[mf], &bhi[nf2][2]);
                }
        }
        __syncthreads();
    }

    // ---- epilogue: registers -> global (float2 per fragment half) ----
    const int mbase = m0 + wm * 64 + (lane >> 2);
    const int cbase = n0 + wn * 32 + (lane & 3) * 2;
#pragma unroll
    for (int mf = 0; mf < 4; ++mf) {
#pragma unroll
        for (int nf = 0; nf < 4; ++nf) {
            const int c = cbase + nf * 8;
#pragma unroll
            for (int h = 0; h < 2; ++h) {
                const int m = mbase + mf * 16 + h * 8;
                float vx = acc[mf][nf][h * 2 + 0];
                float vy = acc[mf][nf][h * 2 + 1];
                if (mode == 0) {
                    vx *= aux[c]; vy *= aux[c + 1];
                    *(float2*)&out0[(size_t)m * CP + c] = make_float2(vx, vy);
                } else if (mode == 1) {
                    if (c < CC) {
                        *(float2*)&out0[(size_t)m * CC + c] = make_float2(vx, vy);
                    } else if (c < 2 * CC) {
                        const int cc = c - CC;
                        vx += aux[cc]; vy += aux[cc + 1];
                        *(float2*)&out1[(size_t)m * CC + cc] = make_float2(vx, vy);
                    }
                } else {
                    if (c < CC) {
                        float2 o = *(const float2*)&out0[(size_t)m * CC + c];
                        o.x += vx; o.y += vy;
                        *(float2*)&out0[(size_t)m * CC + c] = o;
                    }
                }
            }
        }
    }
}

// ---------------- prep / pointwise kernels ----------------
__device__ __forceinline__ void split1(float v, __nv_bfloat16& h, __nv_bfloat16& l) {
    h = __float2bfloat16(v);
    l = __float2bfloat16(v - __bfloat162float(h));
}

__global__ void split_f32_kernel(const float* __restrict__ x,
                                 __nv_bfloat16* __restrict__ hi,
                                 __nv_bfloat16* __restrict__ lo, size_t n)
{
    size_t i = (size_t)blockIdx.x * blockDim.x + threadIdx.x;
    const size_t stride = (size_t)gridDim.x * blockDim.x;
    for (; i < n; i += stride) {
        __nv_bfloat16 h, l;
        split1(x[i], h, l);
        hi[i] = h; lo[i] = l;
    }
}

// B operand: rows [0,1000)=phat, [1000,2000)=W, [2000,2048)=0 ; pn[c] norms
__global__ void __launch_bounds__(256)
build_bmat_kernel(const float* __restrict__ p, const float* __restrict__ w,
                  __nv_bfloat16* __restrict__ bhi, __nv_bfloat16* __restrict__ blo,
                  float* __restrict__ pn)
{
    __shared__ float red[8];
    __shared__ float s_inv;
    const int r = blockIdx.x;
    const int t = threadIdx.x;
    __nv_bfloat16* oh = bhi + (size_t)r * DD;
    __nv_bfloat16* ol = blo + (size_t)r * DD;

    if (r >= 2000) {
        const __nv_bfloat16 z = __float2bfloat16(0.f);
        for (int d = t; d < DD; d += 256) { oh[d] = z; ol[d] = z; }
        return;
    }
    if (r >= 1000) {
        const float* src = w + (size_t)(r - 1000) * DD;
        for (int d = t; d < DD; d += 256) {
            __nv_bfloat16 h, l; split1(src[d], h, l); oh[d] = h; ol[d] = l;
        }
        if (t == 0 && r < CP) pn[r] = 0.f;   // zero pad cols of pn
        return;
    }
    const float* src = p + (size_t)r * DD;
    float s = 0.f;
    for (int d = t; d < DD; d += 256) { float v = src[d]; s += v * v; }
#pragma unroll
    for (int o = 16; o > 0; o >>= 1) s += __shfl_xor_sync(~0u, s, o);
    if ((t & 31) == 0) red[t >> 5] = s;
    __syncthreads();
    if (t == 0) {
        float tot = 0.f;
#pragma unroll
        for (int wv = 0; wv < 8; ++wv) tot += red[wv];
        const float nn = fmaxf(sqrtf(tot), 1e-8f);
        pn[r] = nn;
        s_inv = 1.f / nn;
    }
    __syncthreads();
    const float inv = s_inv;
    for (int d = t; d < DD; d += 256) {
        __nv_bfloat16 h, l; split1(src[d] * inv, h, l); oh[d] = h; ol[d] = l;
    }
}

__global__ void __launch_bounds__(256)
qnorm_kernel(const float* __restrict__ q, float* __restrict__ qn)
{
    __shared__ float red[8];
    const int row = blockIdx.x;
    const float4* x = reinterpret_cast<const float4*>(q + (size_t)row * DD);
    float s = 0.f;
    for (int i = threadIdx.x; i < DD / 4; i += 256) {
        float4 v = x[i];
        s += v.x * v.x + v.y * v.y + v.z * v.z + v.w * v.w;
    }
#pragma unroll
    for (int o = 16; o > 0; o >>= 1) s += __shfl_xor_sync(~0u, s, o);
    if ((threadIdx.x & 31) == 0) red[threadIdx.x >> 5] = s;
    __syncthreads();
    if (threadIdx.x == 0) {
        float tot = 0.f;
#pragma unroll
        for (int w = 0; w < 8; ++w) tot += red[w];
        qn[row] = fmaxf(sqrtf(tot), 1e-8f);
    }
}

__global__ void __launch_bounds__(256)
softmax_mask_kernel(float* __restrict__ scores, const float* __restrict__ qn)
{
    __shared__ float red[8];
    __shared__ float s_max, s_cossum, s_denom;
    const int row = blockIdx.x;
    const int t = threadIdx.x;
    float* s = scores + (size_t)row * CC;
    const float invq = 1.f / qn[row];

    float vals[4];
    float lmax = -1e30f, lsum = 0.f;
#pragma unroll
    for (int it = 0; it < 4; ++it) {
        int i = t + it * 256;
        if (i < CC) {
            float v = s[i] * invq;
            vals[it] = v;
            lmax = fmaxf(lmax, v);
            lsum += v;
        } else vals[it] = 0.f;
    }
#pragma unroll
    for (int o = 16; o > 0; o >>= 1) lmax = fmaxf(lmax, __shfl_xor_sync(~0u, lmax, o));
    if ((t & 31) == 0) red[t >> 5] = lmax;
    __syncthreads();
    if (t == 0) {
        float m = red[0];
#pragma unroll
        for (int w = 1; w < 8; ++w) m = fmaxf(m, red[w]);
        s_max = m;
    }
    __syncthreads();
    const float rmax = s_max;

#pragma unroll
    for (int o = 16; o > 0; o >>= 1) lsum += __shfl_xor_sync(~0u, lsum, o);
    if ((t & 31) == 0) red[t >> 5] = lsum;
    __syncthreads();
    if (t == 0) {
        float m = 0.f;
#pragma unroll
        for (int w = 0; w < 8; ++w) m += red[w];
        s_cossum = m;
    }
    __syncthreads();
    const float rowsum = s_cossum;

    float e[4];
    float lexp = 0.f;
#pragma unroll
    for (int it = 0; it < 4; ++it) {
        int i = t + it * 256;
        if (i < CC) { e[it] = expf((vals[it] - rmax) * 5.0f); lexp += e[it]; }
        else e[it] = 0.f;
    }
#pragma unroll
    for (int o = 16; o > 0; o >>= 1) lexp += __shfl_xor_sync(~0u, lexp, o);
    if ((t & 31) == 0) red[t >> 5] = lexp;
    __syncthreads();
    if (t == 0) {
        float m = 0.f;
#pragma unroll
        for (int w = 0; w < 8; ++w) m += red[w];
        s_denom = m;
    }
    __syncthreads();
    const float scale = (rowsum != 0.0f) ? (1.f / s_denom) : 0.f;
#pragma unroll
    for (int it = 0; it < 4; ++it) {
        int i = t + it * 256;
        if (i < CC) s[i] = e[it] * scale;
    }
}

// attn [BQ x CC] fp32 -> split bf16 [BQ x CP], pad cols zeroed
__global__ void __launch_bounds__(256)
split_attn_kernel(const float* __restrict__ s,
                  __nv_bfloat16* __restrict__ hi, __nv_bfloat16* __restrict__ lo)
{
    const int row = blockIdx.x;
    const int t = threadIdx.x;
    for (int c = t; c < CP; c += 256) {
        const float v = (c < CC) ? s[(size_t)row * CC + c] : 0.f;
        __nv_bfloat16 h, l; split1(v, h, l);
        hi[(size_t)row * CP + c] = h;
        lo[(size_t)row * CP + c] = l;
    }
}

// ---------------------------------------------------------------------------
extern "C" void kernel_launch(void* const* d_in, const int* in_sizes, int n_in,
                              void* d_out, int out_size)
{
    const float* q    = (const float*)d_in[0];
    const float* p    = (const float*)d_in[1];
    const float* w    = (const float*)d_in[2];
    const float* bias = (const float*)d_in[3];
    float* out = (float*)d_out;

    float* logits = out;                       // [BQ, CC]
    float* emb    = out + (size_t)BQ * CC;     // [BQ, DD]

    __nv_bfloat16 *qhi, *qlo, *bhi, *blo, *mthi, *mtlo, *athi, *atlo;
    float *scores, *mt, *qn, *pn;
    cudaGetSymbolAddress((void**)&qhi,  g_q_hi);
    cudaGetSymbolAddress((void**)&qlo,  g_q_lo);
    cudaGetSymbolAddress((void**)&bhi,  g_b_hi);
    cudaGetSymbolAddress((void**)&blo,  g_b_lo);
    cudaGetSymbolAddress((void**)&mthi, g_mt_hi);
    cudaGetSymbolAddress((void**)&mtlo, g_mt_lo);
    cudaGetSymbolAddress((void**)&athi, g_at_hi);
    cudaGetSymbolAddress((void**)&atlo, g_at_lo);
    cudaGetSymbolAddress((void**)&scores, g_scores);
    cudaGetSymbolAddress((void**)&mt,     g_mt);
    cudaGetSymbolAddress((void**)&qn,     g_qn);
    cudaGetSymbolAddress((void**)&pn,     g_pn);

    cudaFuncSetAttribute(mm_split_kernel,
                         cudaFuncAttributeMaxDynamicSharedMemorySize, SMEM_BYTES);

    // operand prep
    split_f32_kernel<<<4096, 256>>>(q, qhi, qlo, (size_t)BQ * DD);
    build_bmat_kernel<<<NBROWS, 256>>>(p, w, bhi, blo, pn);
    qnorm_kernel<<<BQ, 256>>>(q, qn);

    // GEMM0: Mt[j][c] = pn[c] * sum_d W[j,d] phat[c,d]   (1024x1024x2048)
    mm_split_kernel<<<dim3(8, 8), 256, SMEM_BYTES>>>(
        bhi + (size_t)1000 * DD, blo + (size_t)1000 * DD, DD,
        bhi, blo, DD, DD, mt, nullptr, pn, 0);

    // GEMM1 (fused): scores = q.phat^T ; logits = q.W^T + bias (16384x2048x2048)
    mm_split_kernel<<<dim3(16, 128), 256, SMEM_BYTES>>>(
        qhi, qlo, DD, bhi, blo, DD, DD, scores, logits, bias, 1);

    // softmax (with qn scaling + nonzero mask), in place -> attn
    softmax_mask_kernel<<<BQ, 256>>>(scores, qn);

    // splits for GEMM2
    split_f32_kernel<<<2048, 256>>>(mt, mthi, mtlo, (size_t)CP * CP);
    split_attn_kernel<<<BQ, 256>>>(scores, athi, atlo);

    // GEMM2: logits += attn . Mt rows   (16384x1024x1024)
    mm_split_kernel<<<dim3(8, 128), 256, SMEM_BYTES>>>(
        athi, atlo, CP, mthi, mtlo, CP, CP, logits, nullptr, nullptr, 2);

    // embedding output = querys
    cudaMemcpyAsync(emb, q, (size_t)BQ * DD * sizeof(float), cudaMemcpyDeviceToDevice);
}

// round 6
// speedup vs baseline: 3.6539x; 1.0161x over previous
#include <cuda_runtime.h>
#include <cuda_bf16.h>
#include <cstdint>
#include <math.h>

#define BQ 16384
#define CC 1000
#define DD 2048
#define CP 1024        // padded C
#define NBROWS 2048    // phat rows [0,1000) + W rows [1000,2000) + zero pad

// ---------------- scratch (__device__ globals) ----------------
__device__ __align__(128) __nv_bfloat16 g_q_hi[(size_t)BQ * DD];
__device__ __align__(128) __nv_bfloat16 g_q_lo[(size_t)BQ * DD];
__device__ __align__(128) __nv_bfloat16 g_b_hi[(size_t)NBROWS * DD];
__device__ __align__(128) __nv_bfloat16 g_b_lo[(size_t)NBROWS * DD];
__device__ __align__(128) __nv_bfloat16 g_mt_hi[(size_t)CP * CP];
__device__ __align__(128) __nv_bfloat16 g_mt_lo[(size_t)CP * CP];
__device__ __align__(128) __nv_bfloat16 g_at_hi[(size_t)BQ * CP];
__device__ __align__(128) __nv_bfloat16 g_at_lo[(size_t)BQ * CP];
__device__ float g_scores[(size_t)BQ * CC];
__device__ float g_mt[(size_t)CP * CP];
__device__ float g_qn[BQ];
__device__ float g_pn[CP];

// ---------------- PTX helpers (sm_80-era, no 'a'-gated features) ----------------
__device__ __forceinline__ uint32_t smem_u32(const void* p) {
    uint32_t a;
    asm("{ .reg .u64 t; cvta.to.shared.u64 t, %1; cvt.u32.u64 %0, t; }" : "=r"(a) : "l"(p));
    return a;
}
__device__ __forceinline__ void cp_async16(uint32_t dst, const void* src) {
    asm volatile("cp.async.cg.shared.global [%0], [%1], 16;" :: "r"(dst), "l"(src) : "memory");
}
__device__ __forceinline__ void ldmx4(uint32_t* r, uint32_t addr) {
    asm volatile("ldmatrix.sync.aligned.m8n8.x4.shared.b16 {%0,%1,%2,%3}, [%4];"
                 : "=r"(r[0]), "=r"(r[1]), "=r"(r[2]), "=r"(r[3]) : "r"(addr));
}
__device__ __forceinline__ void mma16816(float* d, const uint32_t* a, const uint32_t* b) {
    asm volatile("mma.sync.aligned.m16n8k16.row.col.f32.bf16.bf16.f32 "
        "{%0,%1,%2,%3}, {%4,%5,%6,%7}, {%8,%9}, {%0,%1,%2,%3};"
        : "+f"(d[0]), "+f"(d[1]), "+f"(d[2]), "+f"(d[3])
        : "r"(a[0]), "r"(a[1]), "r"(a[2]), "r"(a[3]), "r"(b[0]), "r"(b[1]));
}

// ---------------------------------------------------------------------------
// Split-bf16 HMMA GEMM: out[m,n] ~= sum_k A[m,k]*B[n,k] in fp32 via
// acc += Ah*Bh + Ah*Bl + Al*Bh.  128x128 CTA tile, BK=64, 16 warps (4m x 4n),
// warp tile 32x32, 3-stage cp.async pipeline, register accumulators.
// mode 0: out0[m*CP+n]  = v * aux[n]
// mode 1: n<CC -> out0[m*CC+n]=v ; CC<=n<2CC -> out1[m*CC+(n-CC)] = v+aux[n-CC]
// mode 2: n<CC -> out0[m*CC+n] += v
// ---------------------------------------------------------------------------
#define STAGES 3
#define SUB_B 16384                       // one 128-row x 128-byte subtile
#define STAGE_B (4 * SUB_B)               // Ahi, Alo, Bhi, Blo
#define SMEM_BYTES (STAGES * STAGE_B)     // 196608
#define NTHREADS 512

__device__ __forceinline__ void load_stage(
    uint32_t stage, int tid,
    const __nv_bfloat16* Ah, const __nv_bfloat16* Al, int lda, int m0,
    const __nv_bfloat16* Bh, const __nv_bfloat16* Bl, int ldb, int n0, int k0)
{
#pragma unroll
    for (int ii = 0; ii < 8; ++ii) {
        const int sub = ii >> 1;                    // 0:Ah 1:Al 2:Bh 3:Bl
        const int rem = (ii & 1) * NTHREADS + tid;  // 0..1023 within subtile
        const int row = rem >> 3;
        const int ch  = rem & 7;
        const uint32_t dst = stage + sub * SUB_B + row * 128 + ((ch ^ (row & 7)) << 4);
        const __nv_bfloat16* src;
        if (sub == 0)      src = Ah + (size_t)(m0 + row) * lda + k0 + ch * 8;
        else if (sub == 1) src = Al + (size_t)(m0 + row) * lda + k0 + ch * 8;
        else if (sub == 2) src = Bh + (size_t)(n0 + row) * ldb + k0 + ch * 8;
        else               src = Bl + (size_t)(n0 + row) * ldb + k0 + ch * 8;
        cp_async16(dst, src);
    }
    asm volatile("cp.async.commit_group;" ::: "memory");
}

__global__ void __launch_bounds__(NTHREADS, 1)
mm_split_kernel(const __nv_bfloat16* __restrict__ Ahi, const __nv_bfloat16* __restrict__ Alo, int lda,
                const __nv_bfloat16* __restrict__ Bhi, const __nv_bfloat16* __restrict__ Blo, int ldb,
                int K,
                float* __restrict__ out0, float* __restrict__ out1,
                const float* __restrict__ aux, int mode)
{
    extern __shared__ __align__(1024) char smem[];
    const uint32_t sb = smem_u32(smem);
    const int tid  = threadIdx.x;
    const int wid  = tid >> 5, lane = tid & 31;
    const int m0 = blockIdx.y * 128, n0 = blockIdx.x * 128;
    const int nch = K >> 6;
    const int wm = wid & 3;        // 0..3  -> m offset wm*32
    const int wn = wid >> 2;       // 0..3  -> n offset wn*32

    // per-thread ldmatrix row indices (within CTA tile)
    uint32_t a_row[2], b_row[2];
#pragma unroll
    for (int mf = 0; mf < 2; ++mf) a_row[mf] = wm * 32 + mf * 16 + (lane & 15);
#pragma unroll
    for (int nf2 = 0; nf2 < 2; ++nf2)
        b_row[nf2] = wn * 32 + nf2 * 16 + (lane & 7) + ((lane >> 4) << 3);
    const uint32_t a_kc = (lane >> 4);        // 0/1
    const uint32_t b_kc = (lane >> 3) & 1;    // 0/1

    float acc[2][4][4];
#pragma unroll
    for (int i = 0; i < 2; ++i)
#pragma unroll
        for (int j = 0; j < 4; ++j)
#pragma unroll
            for (int r = 0; r < 4; ++r) acc[i][j][r] = 0.f;

    // prologue: stages 0,1
    load_stage(sb, tid, Ahi, Alo, lda, m0, Bhi, Blo, ldb, n0, 0);
    if (nch > 1) load_stage(sb + STAGE_B, tid, Ahi, Alo, lda, m0, Bhi, Blo, ldb, n0, 64);

    for (int i = 0; i < nch; ++i) {
        const int s = i % STAGES;
        if (i + 2 <= nch && nch > 1) asm volatile("cp.async.wait_group 1;" ::: "memory");
        else                         asm volatile("cp.async.wait_group 0;" ::: "memory");
        __syncthreads();

        // prefetch chunk i+2 (its stage was consumed at iter i-1)
        const int nx = i + 2;
        if (nx < nch)
            load_stage(sb + (nx % STAGES) * STAGE_B, tid,
                       Ahi, Alo, lda, m0, Bhi, Blo, ldb, n0, nx * 64);

        const uint32_t sA_hi = sb + s * STAGE_B;
        const uint32_t sA_lo = sA_hi + SUB_B;
        const uint32_t sB_hi = sA_hi + 2 * SUB_B;
        const uint32_t sB_lo = sA_hi + 3 * SUB_B;

#pragma unroll
        for (int st = 0; st < 4; ++st) {
            uint32_t ahi[2][4], alo[2][4];
#pragma unroll
            for (int mf = 0; mf < 2; ++mf) {
                const uint32_t r  = a_row[mf];
                const uint32_t kc = st * 2 + a_kc;
                const uint32_t off = r * 128 + (((kc ^ (r & 7))) << 4);
                ldmx4(ahi[mf], sA_hi + off);
                ldmx4(alo[mf], sA_lo + off);
            }
            uint32_t bhi[2][4], blo[2][4];
#pragma unroll
            for (int nf2 = 0; nf2 < 2; ++nf2) {
                const uint32_t r  = b_row[nf2];
                const uint32_t kc = st * 2 + b_kc;
                const uint32_t off = r * 128 + (((kc ^ (r & 7))) << 4);
                ldmx4(bhi[nf2], sB_hi + off);
                ldmx4(blo[nf2], sB_lo + off);
            }
#pragma unroll
            for (int mf = 0; mf < 2; ++mf)
#pragma unroll
                for (int nf2 = 0; nf2 < 2; ++nf2) {
                    mma16816(acc[mf][nf2 * 2],     ahi[mf], &bhi[nf2][0]);
                    mma16816(acc[mf][nf2 * 2],     ahi[mf], &blo[nf2][0]);
                    mma16816(acc[mf][nf2 * 2],     alo[mf], &bhi[nf2][0]);
                    mma16816(acc[mf][nf2 * 2 + 1], ahi[mf], &bhi[nf2][2]);
                    mma16816(acc[mf][nf2 * 2 + 1], ahi[mf], &blo[nf2][2]);
                    mma16816(acc[mf][nf2 * 2 + 1], alo[mf], &bhi[nf2][2]);
                }
        }
        __syncthreads();
    }

    // ---- epilogue: registers -> global (float2 per fragment half) ----
    const int mbase = m0 + wm * 32 + (lane >> 2);
    const int cbase = n0 + wn * 32 + (lane & 3) * 2;
#pragma unroll
    for (int mf = 0; mf < 2; ++mf) {
#pragma unroll
        for (int nf = 0; nf < 4; ++nf) {
            const int c = cbase + nf * 8;
#pragma unroll
            for (int h = 0; h < 2; ++h) {
                const int m = mbase + mf * 16 + h * 8;
                float vx = acc[mf][nf][h * 2 + 0];
                float vy = acc[mf][nf][h * 2 + 1];
                if (mode == 0) {
                    vx *= aux[c]; vy *= aux[c + 1];
                    *(float2*)&out0[(size_t)m * CP + c] = make_float2(vx, vy);
                } else if (mode == 1) {
                    if (c < CC) {
                        *(float2*)&out0[(size_t)m * CC + c] = make_float2(vx, vy);
                    } else if (c < 2 * CC) {
                        const int cc = c - CC;
                        vx += aux[cc]; vy += aux[cc + 1];
                        *(float2*)&out1[(size_t)m * CC + cc] = make_float2(vx, vy);
                    }
                } else {
                    if (c < CC) {
                        float2 o = *(const float2*)&out0[(size_t)m * CC + c];
                        o.x += vx; o.y += vy;
                        *(float2*)&out0[(size_t)m * CC + c] = o;
                    }
                }
            }
        }
    }
}

// ---------------- prep / pointwise kernels ----------------
__device__ __forceinline__ void split1(float v, __nv_bfloat16& h, __nv_bfloat16& l) {
    h = __float2bfloat16(v);
    l = __float2bfloat16(v - __bfloat162float(h));
}

__global__ void split_f32_kernel(const float* __restrict__ x,
                                 __nv_bfloat16* __restrict__ hi,
                                 __nv_bfloat16* __restrict__ lo, size_t n)
{
    size_t i = (size_t)blockIdx.x * blockDim.x + threadIdx.x;
    const size_t stride = (size_t)gridDim.x * blockDim.x;
    for (; i < n; i += stride) {
        __nv_bfloat16 h, l;
        split1(x[i], h, l);
        hi[i] = h; lo[i] = l;
    }
}

// B operand: rows [0,1000)=phat, [1000,2000)=W, [2000,2048)=0 ; pn[c] norms
__global__ void __launch_bounds__(256)
build_bmat_kernel(const float* __restrict__ p, const float* __restrict__ w,
                  __nv_bfloat16* __restrict__ bhi, __nv_bfloat16* __restrict__ blo,
                  float* __restrict__ pn)
{
    __shared__ float red[8];
    __shared__ float s_inv;
    const int r = blockIdx.x;
    const int t = threadIdx.x;
    __nv_bfloat16* oh = bhi + (size_t)r * DD;
    __nv_bfloat16* ol = blo + (size_t)r * DD;

    if (r >= 2000) {
        const __nv_bfloat16 z = __float2bfloat16(0.f);
        for (int d = t; d < DD; d += 256) { oh[d] = z; ol[d] = z; }
        return;
    }
    if (r >= 1000) {
        const float* src = w + (size_t)(r - 1000) * DD;
        for (int d = t; d < DD; d += 256) {
            __nv_bfloat16 h, l; split1(src[d], h, l); oh[d] = h; ol[d] = l;
        }
        if (t == 0 && r < CP) pn[r] = 0.f;   // zero pad cols of pn
        return;
    }
    const float* src = p + (size_t)r * DD;
    float s = 0.f;
    for (int d = t; d < DD; d += 256) { float v = src[d]; s += v * v; }
#pragma unroll
    for (int o = 16; o > 0; o >>= 1) s += __shfl_xor_sync(~0u, s, o);
    if ((t & 31) == 0) red[t >> 5] = s;
    __syncthreads();
    if (t == 0) {
        float tot = 0.f;
#pragma unroll
        for (int wv = 0; wv < 8; ++wv) tot += red[wv];
        const float nn = fmaxf(sqrtf(tot), 1e-8f);
        pn[r] = nn;
        s_inv = 1.f / nn;
    }
    __syncthreads();
    const float inv = s_inv;
    for (int d = t; d < DD; d += 256) {
        __nv_bfloat16 h, l; split1(src[d] * inv, h, l); oh[d] = h; ol[d] = l;
    }
}

__global__ void __launch_bounds__(256)
qnorm_kernel(const float* __restrict__ q, float* __restrict__ qn)
{
    __shared__ float red[8];
    const int row = blockIdx.x;
    const float4* x = reinterpret_cast<const float4*>(q + (size_t)row * DD);
    float s = 0.f;
    for (int i = threadIdx.x; i < DD / 4; i += 256) {
        float4 v = x[i];
        s += v.x * v.x + v.y * v.y + v.z * v.z + v.w * v.w;
    }
#pragma unroll
    for (int o = 16; o > 0; o >>= 1) s += __shfl_xor_sync(~0u, s, o);
    if ((threadIdx.x & 31) == 0) red[threadIdx.x >> 5] = s;
    __syncthreads();
    if (threadIdx.x == 0) {
        float tot = 0.f;
#pragma unroll
        for (int w = 0; w < 8; ++w) tot += red[w];
        qn[row] = fmaxf(sqrtf(tot), 1e-8f);
    }
}

__global__ void __launch_bounds__(256)
softmax_mask_kernel(float* __restrict__ scores, const float* __restrict__ qn)
{
    __shared__ float red[8];
    __shared__ float s_max, s_cossum, s_denom;
    const int row = blockIdx.x;
    const int t = threadIdx.x;
    float* s = scores + (size_t)row * CC;
    const float invq = 1.f / qn[row];

    float vals[4];
    float lmax = -1e30f, lsum = 0.f;
#pragma unroll
    for (int it = 0; it < 4; ++it) {
        int i = t + it * 256;
        if (i < CC) {
            float v = s[i] * invq;
            vals[it] = v;
            lmax = fmaxf(lmax, v);
            lsum += v;
        } else vals[it] = 0.f;
    }
#pragma unroll
    for (int o = 16; o > 0; o >>= 1) lmax = fmaxf(lmax, __shfl_xor_sync(~0u, lmax, o));
    if ((t & 31) == 0) red[t >> 5] = lmax;
    __syncthreads();
    if (t == 0) {
        float m = red[0];
#pragma unroll
        for (int w = 1; w < 8; ++w) m = fmaxf(m, red[w]);
        s_max = m;
    }
    __syncthreads();
    const float rmax = s_max;

#pragma unroll
    for (int o = 16; o > 0; o >>= 1) lsum += __shfl_xor_sync(~0u, lsum, o);
    if ((t & 31) == 0) red[t >> 5] = lsum;
    __syncthreads();
    if (t == 0) {
        float m = 0.f;
#pragma unroll
        for (int w = 0; w < 8; ++w) m += red[w];
        s_cossum = m;
    }
    __syncthreads();
    const float rowsum = s_cossum;

    float e[4];
    float lexp = 0.f;
#pragma unroll
    for (int it = 0; it < 4; ++it) {
        int i = t + it * 256;
        if (i < CC) { e[it] = expf((vals[it] - rmax) * 5.0f); lexp += e[it]; }
        else e[it] = 0.f;
    }
#pragma unroll
    for (int o = 16; o > 0; o >>= 1) lexp += __shfl_xor_sync(~0u, lexp, o);
    if ((t & 31) == 0) red[t >> 5] = lexp;
    __syncthreads();
    if (t == 0) {
        float m = 0.f;
#pragma unroll
        for (int w = 0; w < 8; ++w) m += red[w];
        s_denom = m;
    }
    __syncthreads();
    const float scale = (rowsum != 0.0f) ? (1.f / s_denom) : 0.f;
#pragma unroll
    for (int it = 0; it < 4; ++it) {
        int i = t + it * 256;
        if (i < CC) s[i] = e[it] * scale;
    }
}

// attn [BQ x CC] fp32 -> split bf16 [BQ x CP], pad cols zeroed
__global__ void __launch_bounds__(256)
split_attn_kernel(const float* __restrict__ s,
                  __nv_bfloat16* __restrict__ hi, __nv_bfloat16* __restrict__ lo)
{
    const int row = blockIdx.x;
    const int t = threadIdx.x;
    for (int c = t; c < CP; c += 256) {
        const float v = (c < CC) ? s[(size_t)row * CC + c] : 0.f;
        __nv_bfloat16 h, l; split1(v, h, l);
        hi[(size_t)row * CP + c] = h;
        lo[(size_t)row * CP + c] = l;
    }
}

// ---------------------------------------------------------------------------
extern "C" void kernel_launch(void* const* d_in, const int* in_sizes, int n_in,
                              void* d_out, int out_size)
{
    const float* q    = (const float*)d_in[0];
    const float* p    = (const float*)d_in[1];
    const float* w    = (const float*)d_in[2];
    const float* bias = (const float*)d_in[3];
    float* out = (float*)d_out;

    float* logits = out;                       // [BQ, CC]
    float* emb    = out + (size_t)BQ * CC;     // [BQ, DD]

    __nv_bfloat16 *qhi, *qlo, *bhi, *blo, *mthi, *mtlo, *athi, *atlo;
    float *scores, *mt, *qn, *pn;
    cudaGetSymbolAddress((void**)&qhi,  g_q_hi);
    cudaGetSymbolAddress((void**)&qlo,  g_q_lo);
    cudaGetSymbolAddress((void**)&bhi,  g_b_hi);
    cudaGetSymbolAddress((void**)&blo,  g_b_lo);
    cudaGetSymbolAddress((void**)&mthi, g_mt_hi);
    cudaGetSymbolAddress((void**)&mtlo, g_mt_lo);
    cudaGetSymbolAddress((void**)&athi, g_at_hi);
    cudaGetSymbolAddress((void**)&atlo, g_at_lo);
    cudaGetSymbolAddress((void**)&scores, g_scores);
    cudaGetSymbolAddress((void**)&mt,     g_mt);
    cudaGetSymbolAddress((void**)&qn,     g_qn);
    cudaGetSymbolAddress((void**)&pn,     g_pn);

    cudaFuncSetAttribute(mm_split_kernel,
                         cudaFuncAttributeMaxDynamicSharedMemorySize, SMEM_BYTES);

    // operand prep
    split_f32_kernel<<<4096, 256>>>(q, qhi, qlo, (size_t)BQ * DD);
    build_bmat_kernel<<<NBROWS, 256>>>(p, w, bhi, blo, pn);
    qnorm_kernel<<<BQ, 256>>>(q, qn);

    // GEMM0: Mt[j][c] = pn[c] * sum_d W[j,d] phat[c,d]   (1024x1024x2048)
    mm_split_kernel<<<dim3(8, 8), NTHREADS, SMEM_BYTES>>>(
        bhi + (size_t)1000 * DD, blo + (size_t)1000 * DD, DD,
        bhi, blo, DD, DD, mt, nullptr, pn, 0);

    // GEMM1 (fused): scores = q.phat^T ; logits = q.W^T + bias (16384x2048x2048)
    mm_split_kernel<<<dim3(16, 128), NTHREADS, SMEM_BYTES>>>(
        qhi, qlo, DD, bhi, blo, DD, DD, scores, logits, bias, 1);

    // softmax (with qn scaling + nonzero mask), in place -> attn
    softmax_mask_kernel<<<BQ, 256>>>(scores, qn);

    // splits for GEMM2
    split_f32_kernel<<<2048, 256>>>(mt, mthi, mtlo, (size_t)CP * CP);
    split_attn_kernel<<<BQ, 256>>>(scores, athi, atlo);

    // GEMM2: logits += attn . Mt rows   (16384x1024x1024)
    mm_split_kernel<<<dim3(8, 128), NTHREADS, SMEM_BYTES>>>(
        athi, atlo, CP, mthi, mtlo, CP, CP, logits, nullptr, nullptr, 2);

    // embedding output = querys
    cudaMemcpyAsync(emb, q, (size_t)BQ * DD * sizeof(float), cudaMemcpyDeviceToDevice);
}